// round 12
// baseline (speedup 1.0000x reference)
#include <cuda_runtime.h>
#include <cuda_fp16.h>

#define B_     4
#define CIN    256
#define CO_    64
#define N_     576   // 24*24
#define CV_    256
#define KSPLIT 6
#define CHUNKS 3     // 3 chunks of 32 k per split (6*3*32 = 576)

// Scratch (device globals — no allocation allowed)
__device__ unsigned g_kph[B_ * N_ * 32];   // (B, Nk, 32) half2 pairs over c
__device__ unsigned g_qph[B_ * N_ * 32];   // (B, Nq, 32)

// ---------- packed helpers ----------
__device__ __forceinline__ unsigned long long pack2(float lo, float hi) {
    unsigned long long r;
    asm("mov.b64 %0, {%1, %2};" : "=l"(r) : "f"(lo), "f"(hi));
    return r;
}
__device__ __forceinline__ void unpack2(unsigned long long v, float& lo, float& hi) {
    asm("mov.b64 {%0, %1}, %2;" : "=f"(lo), "=f"(hi) : "l"(v));
}
__device__ __forceinline__ unsigned long long ffma2(unsigned long long a,
                                                    unsigned long long b,
                                                    unsigned long long c) {
    unsigned long long d;
    asm("fma.rn.f32x2 %0, %1, %2, %3;" : "=l"(d) : "l"(a), "l"(b), "l"(c));
    return d;
}
__device__ __forceinline__ float tanhfast(float x) {
    float y;
    asm("tanh.approx.f32 %0, %1;" : "=f"(y) : "f"(x));
    return y;
}
__device__ __forceinline__ unsigned tanh_h2(unsigned x) {
    unsigned y;
    asm("tanh.approx.f16x2 %0, %1;" : "=r"(y) : "r"(x));
    return y;
}
__device__ __forceinline__ __half2 u2h(unsigned u) { return *(__half2*)&u; }
__device__ __forceinline__ unsigned h2u(__half2 h) { return *(unsigned*)&h; }

// ============================================================================
// Kernel A: projections -> half2, PLUS zero-init of d_out (kind-0 blocks).
// grid (18 n-tiles of 32, B, 2), 512 thr, __launch_bounds__(512,1).
// ============================================================================
#define PROJ_SMEM_BYTES ((256 * 32 + 256 * 66) * 4)

__global__ void __launch_bounds__(512, 1) proj_kernel(
    const float* __restrict__ key, const float* __restrict__ query,
    const float* __restrict__ Wk,  const float* __restrict__ bk,
    const float* __restrict__ Wq,  const float* __restrict__ bq,
    float4* __restrict__ out_zero)
{
    extern __shared__ float smem[];
    float (*sX)[32] = (float (*)[32])smem;               // [256 ch][32 n]
    float (*sW)[66] = (float (*)[66])(smem + 256 * 32);  // [256 ch][64 c]

    const int kind = blockIdx.z;
    const float* X    = kind ? query : key;    // (B, CIN, N)
    const float* W    = kind ? Wq    : Wk;     // (CO, CIN)
    const float* bias = kind ? bq    : bk;
    unsigned* outp    = kind ? g_qph : g_kph;  // (B, N, 32) half2

    const int b  = blockIdx.y;
    const int n0 = blockIdx.x * 32;
    const int t  = threadIdx.x;

    // ---- zero d_out (kind-0 blocks; 72 blocks x 512 thr x 4 float4) ----
    if (kind == 0) {
        const int idx = (b * 18 + blockIdx.x) * 512 + t;   // 0..36863
        #pragma unroll
        for (int i = 0; i < 4; i++)
            out_zero[i * 36864 + idx] = make_float4(0.f, 0.f, 0.f, 0.f);
    }

    {   // stage X: 256ch x 32n as float4 (coalesced)
        const int n4  = (t & 7) * 4;
        const int chb = t >> 3;                  // 0..63
        #pragma unroll
        for (int i = 0; i < 4; i++) {
            const int ch = chb + i * 64;
            *(float4*)&sX[ch][n4] =
                *(const float4*)&X[((size_t)(b * CIN + ch)) * N_ + n0 + n4];
        }
    }
    {   // stage W transposed: sW[ch][c]
        const int ch = t & 255;
        const int cb = (t >> 8) * 32;            // 0 or 32
        #pragma unroll 8
        for (int j = 0; j < 32; j++) {
            const int cr = cb + j;
            sW[ch][cr] = W[cr * CIN + ch];
        }
    }
    __syncthreads();

    const int ng = t & 15;           // n = 2*ng, 2*ng+1
    const int c  = (t >> 4) * 2;     // c, c+1

    unsigned long long a0 = 0ull, a1 = 0ull;

    for (int ch0 = 0; ch0 < CIN; ch0 += 8) {
        unsigned long long xps[8];
        float2 ws[8];
        #pragma unroll
        for (int i = 0; i < 8; i++) {
            xps[i] = *(const unsigned long long*)&sX[ch0 + i][ng * 2];
            ws[i]  = *(const float2*)&sW[ch0 + i][c];
        }
        #pragma unroll
        for (int i = 0; i < 8; i++) {
            a0 = ffma2(xps[i], pack2(ws[i].x, ws[i].x), a0);
            a1 = ffma2(xps[i], pack2(ws[i].y, ws[i].y), a1);
        }
    }

    const float bv0 = bias[c];
    const float bv1 = bias[c + 1];
    float c0n0, c0n1, c1n0, c1n1;
    unpack2(a0, c0n0, c0n1);
    unpack2(a1, c1n0, c1n1);

    const int n  = n0 + ng * 2;
    const int cc = c >> 1;
    outp[((size_t)b * N_ + n + 0) * 32 + cc] =
        h2u(__floats2half2_rn(c0n0 + bv0, c1n0 + bv1));
    outp[((size_t)b * N_ + n + 1) * 32 + cc] =
        h2u(__floats2half2_rn(c0n1 + bv0, c1n1 + bv1));
}

// ============================================================================
// Kernel B (FUSED v5, instruction diet): block = (32 q, 96 k-range, b).
// grid (18, 6, 4) = 432 blocks, 256 thr, ~3 blocks/SM resident.
// q-tile 32 halves sV staging + FMA-LDS per output; attn scores stored
// DUPLICATED (float2 (a,a)) so FFMA2 b-operands load pre-packed (no movs).
// Thread: attn = 4 scores (ka, qa+8i); FMA = 8c x 4q (16 FFMA2/kk).
// ============================================================================
__global__ void __launch_bounds__(256, 3) fused_kernel(
    const float* __restrict__ value, const float* __restrict__ wf,
    const float* __restrict__ bfp, float* __restrict__ out)
{
    __shared__ unsigned sqh[32][34];                 // q tile half2 pairs
    __shared__ unsigned swh[32];
    __shared__ unsigned skh[32][34];                 // current k chunk
    __shared__ __align__(16) float2 sA2[32][34];     // duplicated attn [k][q]
    __shared__ __align__(16) float  sV[32][260];     // V chunk [k][c]

    const int b  = blockIdx.z;
    const int q0 = blockIdx.x * 32;
    const int kbase = blockIdx.y * (CHUNKS * 32);
    const int t  = threadIdx.x;

    // ---- stage q tile (32 x 16 uint2) + wf (once) ----
    #pragma unroll
    for (int j = 0; j < 2; j++) {
        const int idx = t + j * 256;
        const int r = idx >> 4;              // 0..31
        const int u = (idx & 15) * 2;
        *(uint2*)&sqh[r][u] =
            *(const uint2*)&g_qph[((size_t)b * N_ + q0 + r) * 32 + u];
    }
    if (t < 32) {
        const float2 w = *(const float2*)&wf[t * 2];
        swh[t] = h2u(__floats2half2_rn(w.x, w.y));
    }
    const float bf = __ldg(bfp);

    // attn mapping: scores (ka, qa + 8i), i = 0..3
    const int ka = t & 31;
    const int qa = t >> 5;                 // 0..7

    // FMA mapping: thread = 8c x 4q
    const int qp4 = (t & 7) * 4;           // q, q+1, q+2, q+3
    const int c0  = (t >> 3) * 8;          // 0..248 step 8
    unsigned long long acc[4][4];          // [c-pair][q]
    #pragma unroll
    for (int j = 0; j < 4; j++)
        #pragma unroll
        for (int i = 0; i < 4; i++) acc[j][i] = 0ull;

    // staging mapping for sV
    const int skk = t & 31;
    const int scq = (t >> 5) * 4;          // quad base 0,4,..28

    for (int ch = 0; ch < CHUNKS; ch++) {
        const int k0 = kbase + ch * 32;
        __syncthreads();   // previous FMA done: skh/sV/sA2 reusable

        // ---- stage skh (32x32 uint) ----
        {
            const int kk = t >> 3;
            const int u4 = (t & 7) * 4;
            const uint4 v = *(const uint4*)&g_kph[((size_t)b * N_ + k0 + kk) * 32 + u4];
            *(uint2*)&skh[kk][u4]     = make_uint2(v.x, v.y);
            *(uint2*)&skh[kk][u4 + 2] = make_uint2(v.z, v.w);
        }
        // ---- stage sV: 8 c-quads/thread; 4 coalesced LDG.32 -> 1 STS.128,
        //      in 2-quad batches (8 regs, MLP 8) ----
        {
            const float* vb = value + ((size_t)b * CV_) * N_ + k0 + skk;
            #pragma unroll
            for (int bb = 0; bb < 4; bb++) {
                float4 q[2];
                #pragma unroll
                for (int j = 0; j < 2; j++) {
                    const int cb2 = scq + (bb * 2 + j) * 32;
                    q[j].x = vb[(size_t)(cb2 + 0) * N_];
                    q[j].y = vb[(size_t)(cb2 + 1) * N_];
                    q[j].z = vb[(size_t)(cb2 + 2) * N_];
                    q[j].w = vb[(size_t)(cb2 + 3) * N_];
                }
                #pragma unroll
                for (int j = 0; j < 2; j++) {
                    const int cb2 = scq + (bb * 2 + j) * 32;
                    *(float4*)&sV[skk][cb2] = q[j];
                }
            }
        }
        __syncthreads();

        // ---- attn: 4 scores per thread (shared krow/wv loads) ----
        {
            __half2 ae[4], ao[4];
            #pragma unroll
            for (int i = 0; i < 4; i++) { ae[i] = __float2half2_rn(0.f); ao[i] = ae[i]; }
            const unsigned* __restrict__ krow = skh[ka];
            #pragma unroll 8
            for (int cc = 0; cc < 32; cc += 2) {
                const uint2 kv = *(const uint2*)&krow[cc];
                const uint2 wv = *(const uint2*)&swh[cc];
                #pragma unroll
                for (int i = 0; i < 4; i++) {
                    const uint2 qv = *(const uint2*)&sqh[qa + 8 * i][cc];
                    const unsigned t0 = tanh_h2(h2u(__hadd2(u2h(kv.x), u2h(qv.x))));
                    const unsigned t1 = tanh_h2(h2u(__hadd2(u2h(kv.y), u2h(qv.y))));
                    ae[i] = __hfma2(u2h(t0), u2h(wv.x), ae[i]);
                    ao[i] = __hfma2(u2h(t1), u2h(wv.y), ao[i]);
                }
            }
            #pragma unroll
            for (int i = 0; i < 4; i++) {
                const float2 fe = __half22float2(ae[i]);
                const float2 fo = __half22float2(ao[i]);
                const float s = bf + ((fe.x + fe.y) + (fo.x + fo.y));
                const float sg = fmaf(0.5f, tanhfast(0.5f * s), 0.5f);  // sigmoid
                sA2[ka][qa + 8 * i] = make_float2(sg, sg);              // duplicated
            }
        }
        __syncthreads();

        // ---- FFMA2 contract: 20 instr / 16 FFMA2 per kk ----
        #pragma unroll 4
        for (int kk = 0; kk < 32; kk++) {
            const ulonglong2 aA = *(const ulonglong2*)&sA2[kk][qp4];     // q0,q1 dup
            const ulonglong2 aB = *(const ulonglong2*)&sA2[kk][qp4 + 2]; // q2,q3 dup
            const float* vrow = &sV[kk][c0];
            const ulonglong2 v01 = *(const ulonglong2*)(vrow);      // c0..c0+3
            const ulonglong2 v23 = *(const ulonglong2*)(vrow + 4);  // c0+4..c0+7
            acc[0][0] = ffma2(v01.x, aA.x, acc[0][0]);
            acc[0][1] = ffma2(v01.x, aA.y, acc[0][1]);
            acc[0][2] = ffma2(v01.x, aB.x, acc[0][2]);
            acc[0][3] = ffma2(v01.x, aB.y, acc[0][3]);
            acc[1][0] = ffma2(v01.y, aA.x, acc[1][0]);
            acc[1][1] = ffma2(v01.y, aA.y, acc[1][1]);
            acc[1][2] = ffma2(v01.y, aB.x, acc[1][2]);
            acc[1][3] = ffma2(v01.y, aB.y, acc[1][3]);
            acc[2][0] = ffma2(v23.x, aA.x, acc[2][0]);
            acc[2][1] = ffma2(v23.x, aA.y, acc[2][1]);
            acc[2][2] = ffma2(v23.x, aB.x, acc[2][2]);
            acc[2][3] = ffma2(v23.x, aB.y, acc[2][3]);
            acc[3][0] = ffma2(v23.y, aA.x, acc[3][0]);
            acc[3][1] = ffma2(v23.y, aA.y, acc[3][1]);
            acc[3][2] = ffma2(v23.y, aB.x, acc[3][2]);
            acc[3][3] = ffma2(v23.y, aB.y, acc[3][3]);
        }
    }

    // ---- epilogue: atomicAdd k-partials (out zeroed by proj_kernel) ----
    #pragma unroll
    for (int j = 0; j < 4; j++) {
        #pragma unroll
        for (int i = 0; i < 4; i++) {
            float lo, hi;
            unpack2(acc[j][i], lo, hi);   // c0+2j, c0+2j+1 at q = qp4+i
            float* op = out + ((size_t)(b * CV_ + c0 + 2 * j)) * N_ + q0 + qp4 + i;
            atomicAdd(op, lo);
            atomicAdd(op + N_, hi);
        }
    }
}

// ============================================================================
extern "C" void kernel_launch(void* const* d_in, const int* in_sizes, int n_in,
                              void* d_out, int out_size)
{
    const float* key   = (const float*)d_in[0];
    const float* query = (const float*)d_in[1];
    const float* value = (const float*)d_in[2];
    const float* Wk    = (const float*)d_in[3];
    const float* bk    = (const float*)d_in[4];
    const float* Wq    = (const float*)d_in[5];
    const float* bq    = (const float*)d_in[6];
    const float* wf    = (const float*)d_in[7];
    const float* bf    = (const float*)d_in[8];
    float* out = (float*)d_out;

    static int attr_set = 0;
    if (!attr_set) {
        cudaFuncSetAttribute(proj_kernel,
                             cudaFuncAttributeMaxDynamicSharedMemorySize,
                             PROJ_SMEM_BYTES);
        attr_set = 1;
    }

    proj_kernel<<<dim3(N_ / 32, B_, 2), 512, PROJ_SMEM_BYTES>>>(
        key, query, Wk, bk, Wq, bq, (float4*)out);
    fused_kernel<<<dim3(N_ / 32, KSPLIT, B_), 256>>>(value, wf, bf, out);
}

// round 13
// speedup vs baseline: 1.3755x; 1.3755x over previous
#include <cuda_runtime.h>
#include <cuda_fp16.h>

#define B_     4
#define CIN    256
#define CO_    64
#define N_     576   // 24*24
#define CV_    256
#define KSPLIT 3
#define CHUNKS 6     // 6 chunks of 32 k per split (3*6*32 = 576)

// Scratch (device globals — no allocation allowed)
__device__ unsigned g_kph[B_ * N_ * 32];   // (B, Nk, 32) half2 pairs over c
__device__ unsigned g_qph[B_ * N_ * 32];   // (B, Nq, 32)
__device__ __half   g_vh[B_ * CV_ * N_];   // fp16 copy of value

// ---------- packed helpers ----------
__device__ __forceinline__ unsigned long long pack2(float lo, float hi) {
    unsigned long long r;
    asm("mov.b64 %0, {%1, %2};" : "=l"(r) : "f"(lo), "f"(hi));
    return r;
}
__device__ __forceinline__ void unpack2(unsigned long long v, float& lo, float& hi) {
    asm("mov.b64 {%0, %1}, %2;" : "=f"(lo), "=f"(hi) : "l"(v));
}
__device__ __forceinline__ unsigned long long ffma2(unsigned long long a,
                                                    unsigned long long b,
                                                    unsigned long long c) {
    unsigned long long d;
    asm("fma.rn.f32x2 %0, %1, %2, %3;" : "=l"(d) : "l"(a), "l"(b), "l"(c));
    return d;
}
__device__ __forceinline__ float tanhfast(float x) {
    float y;
    asm("tanh.approx.f32 %0, %1;" : "=f"(y) : "f"(x));
    return y;
}
__device__ __forceinline__ unsigned tanh_h2(unsigned x) {
    unsigned y;
    asm("tanh.approx.f16x2 %0, %1;" : "=r"(y) : "r"(x));
    return y;
}
__device__ __forceinline__ __half2 u2h(unsigned u) { return *(__half2*)&u; }
__device__ __forceinline__ unsigned h2u(__half2 h) { return *(unsigned*)&h; }
__device__ __forceinline__ unsigned su32(const void* p) {
    return (unsigned)__cvta_generic_to_shared(p);
}

// ============================================================================
// Kernel A: kind 0/1: projections -> half2 (+ kind-0 zero-inits d_out).
//           kind 2: convert V -> fp16 (g_vh).
// grid (18, B, 3), 512 thr, __launch_bounds__(512,1).
// ============================================================================
#define PROJ_SMEM_BYTES ((256 * 32 + 256 * 66) * 4)

__global__ void __launch_bounds__(512, 1) proj_kernel(
    const float* __restrict__ key, const float* __restrict__ query,
    const float* __restrict__ value,
    const float* __restrict__ Wk,  const float* __restrict__ bk,
    const float* __restrict__ Wq,  const float* __restrict__ bq,
    float4* __restrict__ out_zero)
{
    const int kind = blockIdx.z;
    const int b  = blockIdx.y;
    const int n0 = blockIdx.x * 32;
    const int t  = threadIdx.x;

    if (kind == 2) {   // ---- V -> fp16 ----
        #pragma unroll
        for (int i = 0; i < 16; i++) {
            const int idx = i * 512 + t;          // 0..8191 = 256c x 32n
            const int c = idx >> 5;
            const int n = n0 + (idx & 31);
            g_vh[((size_t)(b * CV_ + c)) * N_ + n] =
                __float2half_rn(value[((size_t)(b * CV_ + c)) * N_ + n]);
        }
        return;
    }

    extern __shared__ float smem[];
    float (*sX)[32] = (float (*)[32])smem;               // [256 ch][32 n]
    float (*sW)[66] = (float (*)[66])(smem + 256 * 32);  // [256 ch][64 c]

    const float* X    = kind ? query : key;    // (B, CIN, N)
    const float* W    = kind ? Wq    : Wk;     // (CO, CIN)
    const float* bias = kind ? bq    : bk;
    unsigned* outp    = kind ? g_qph : g_kph;  // (B, N, 32) half2

    // ---- zero d_out (kind-0 blocks; 72 blocks x 512 thr x 4 float4) ----
    if (kind == 0) {
        const int idx = (b * 18 + blockIdx.x) * 512 + t;   // 0..36863
        #pragma unroll
        for (int i = 0; i < 4; i++)
            out_zero[i * 36864 + idx] = make_float4(0.f, 0.f, 0.f, 0.f);
    }

    {   // stage X: 256ch x 32n as float4 (coalesced)
        const int n4  = (t & 7) * 4;
        const int chb = t >> 3;                  // 0..63
        #pragma unroll
        for (int i = 0; i < 4; i++) {
            const int ch = chb + i * 64;
            *(float4*)&sX[ch][n4] =
                *(const float4*)&X[((size_t)(b * CIN + ch)) * N_ + n0 + n4];
        }
    }
    {   // stage W transposed: sW[ch][c]
        const int ch = t & 255;
        const int cb = (t >> 8) * 32;            // 0 or 32
        #pragma unroll 8
        for (int j = 0; j < 32; j++) {
            const int cr = cb + j;
            sW[ch][cr] = W[cr * CIN + ch];
        }
    }
    __syncthreads();

    const int ng = t & 15;           // n = 2*ng, 2*ng+1
    const int c  = (t >> 4) * 2;     // c, c+1

    unsigned long long a0 = 0ull, a1 = 0ull;

    for (int ch0 = 0; ch0 < CIN; ch0 += 8) {
        unsigned long long xps[8];
        float2 ws[8];
        #pragma unroll
        for (int i = 0; i < 8; i++) {
            xps[i] = *(const unsigned long long*)&sX[ch0 + i][ng * 2];
            ws[i]  = *(const float2*)&sW[ch0 + i][c];
        }
        #pragma unroll
        for (int i = 0; i < 8; i++) {
            a0 = ffma2(xps[i], pack2(ws[i].x, ws[i].x), a0);
            a1 = ffma2(xps[i], pack2(ws[i].y, ws[i].y), a1);
        }
    }

    const float bv0 = bias[c];
    const float bv1 = bias[c + 1];
    float c0n0, c0n1, c1n0, c1n1;
    unpack2(a0, c0n0, c0n1);
    unpack2(a1, c1n0, c1n1);

    const int n  = n0 + ng * 2;
    const int cc = c >> 1;
    outp[((size_t)b * N_ + n + 0) * 32 + cc] =
        h2u(__floats2half2_rn(c0n0 + bv0, c1n0 + bv1));
    outp[((size_t)b * N_ + n + 1) * 32 + cc] =
        h2u(__floats2half2_rn(c0n1 + bv0, c1n1 + bv1));
}

// ============================================================================
// Kernel B (FUSED v6, HMMA): block = (16 q, 192 k-range, b), grid (36,3,4)=432.
// Per 32k-chunk: stage skh + sVh(fp16) | attn (f16x2 tanh) -> sAh fp16 [k][q]
// | ldmatrix + mma.m16n8k16 accumulate D (fp32, regs, all chunks).
// Epilogue: 16 atomicAdds of the k-partial (out pre-zeroed by proj).
// ============================================================================
__global__ void __launch_bounds__(256, 3) fused_kernel(
    const float* __restrict__ wf, const float* __restrict__ bfp,
    float* __restrict__ out)
{
    __shared__ unsigned sqh[16][34];                 // q tile half2 pairs
    __shared__ unsigned swh[32];
    __shared__ unsigned skh[32][34];                 // current k chunk (half2)
    __shared__ __align__(16) __half sAh[32][24];     // attn fp16 [k][q], 48B rows
    __shared__ __align__(16) __half sVh[256][40];    // V fp16 [c][k], 80B rows

    const int b  = blockIdx.z;
    const int q0 = blockIdx.x * 16;
    const int kbase = blockIdx.y * (CHUNKS * 32);
    const int t  = threadIdx.x;
    const int lane = t & 31;
    const int w    = t >> 5;

    // ---- stage q tile (16 x 32 uint) + wf (once) ----
    {
        const int r = t >> 4;              // 0..15
        const int u = (t & 15) * 2;
        *(uint2*)&sqh[r][u] =
            *(const uint2*)&g_qph[((size_t)b * N_ + q0 + r) * 32 + u];
    }
    if (t < 32) {
        const float2 wv = *(const float2*)&wf[t * 2];
        swh[t] = h2u(__floats2half2_rn(wv.x, wv.y));
    }
    const float bf = __ldg(bfp);

    // attn mapping: scores (ka, qa) and (ka, qa+8)
    const int ka = lane;
    const int qa = w;                      // 0..7

    // mma accumulators: warp owns c = w*32..w*32+31 (2 c-tiles), 2 q-tiles
    float d[2][2][4];
    #pragma unroll
    for (int ct = 0; ct < 2; ct++)
        #pragma unroll
        for (int qt = 0; qt < 2; qt++)
            #pragma unroll
            for (int i = 0; i < 4; i++) d[ct][qt][i] = 0.f;

    for (int ch = 0; ch < CHUNKS; ch++) {
        const int k0 = kbase + ch * 32;
        __syncthreads();   // previous mma reads done: skh/sVh/sAh reusable

        // ---- stage skh (32x32 uint) ----
        {
            const int kk = t >> 3;
            const int u4 = (t & 7) * 4;
            const uint4 v = *(const uint4*)&g_kph[((size_t)b * N_ + k0 + kk) * 32 + u4];
            *(uint2*)&skh[kk][u4]     = make_uint2(v.x, v.y);
            *(uint2*)&skh[kk][u4 + 2] = make_uint2(v.z, v.w);
        }
        // ---- stage sVh: 256c x 32k fp16 (uint4 = 8 halves, coalesced) ----
        {
            const __half* vb = g_vh + ((size_t)b * CV_) * N_ + k0;
            #pragma unroll
            for (int i = 0; i < 4; i++) {
                const int idx = i * 256 + t;     // 0..1023 uint4
                const int c   = idx >> 2;
                const int kq  = (idx & 3) * 8;
                *(uint4*)&sVh[c][kq] = *(const uint4*)(vb + (size_t)c * N_ + kq);
            }
        }
        __syncthreads();

        // ---- attn: 2 scores per thread -> sAh fp16 ----
        {
            __half2 aeA = __float2half2_rn(0.f), aoA = aeA;
            __half2 aeB = aeA, aoB = aeA;
            const unsigned* __restrict__ krow  = skh[ka];
            const unsigned* __restrict__ qrowA = sqh[qa];
            const unsigned* __restrict__ qrowB = sqh[qa + 8];
            #pragma unroll 8
            for (int cc = 0; cc < 32; cc += 2) {
                const uint2 kv = *(const uint2*)&krow[cc];
                const uint2 wv = *(const uint2*)&swh[cc];
                const uint2 qA = *(const uint2*)&qrowA[cc];
                const uint2 qB = *(const uint2*)&qrowB[cc];
                const unsigned tA0 = tanh_h2(h2u(__hadd2(u2h(kv.x), u2h(qA.x))));
                const unsigned tA1 = tanh_h2(h2u(__hadd2(u2h(kv.y), u2h(qA.y))));
                const unsigned tB0 = tanh_h2(h2u(__hadd2(u2h(kv.x), u2h(qB.x))));
                const unsigned tB1 = tanh_h2(h2u(__hadd2(u2h(kv.y), u2h(qB.y))));
                aeA = __hfma2(u2h(tA0), u2h(wv.x), aeA);
                aoA = __hfma2(u2h(tA1), u2h(wv.y), aoA);
                aeB = __hfma2(u2h(tB0), u2h(wv.x), aeB);
                aoB = __hfma2(u2h(tB1), u2h(wv.y), aoB);
            }
            const float2 feA = __half22float2(aeA);
            const float2 foA = __half22float2(aoA);
            const float2 feB = __half22float2(aeB);
            const float2 foB = __half22float2(aoB);
            const float sAv = bf + ((feA.x + feA.y) + (foA.x + foA.y));
            const float sBv = bf + ((feB.x + feB.y) + (foB.x + foB.y));
            sAh[ka][qa]     = __float2half_rn(fmaf(0.5f, tanhfast(0.5f * sAv), 0.5f));
            sAh[ka][qa + 8] = __float2half_rn(fmaf(0.5f, tanhfast(0.5f * sBv), 0.5f));
        }
        __syncthreads();

        // ---- tensor-core contract: D += V[c,k] * A[k,q] ----
        {
            // B frags: [ktile][qtile], ldmatrix.x2.trans on sAh rows [k][q]
            unsigned bfr[2][2][2];
            #pragma unroll
            for (int kt = 0; kt < 2; kt++)
                #pragma unroll
                for (int qt = 0; qt < 2; qt++) {
                    const unsigned addr = su32(&sAh[kt * 16 + (lane & 15)][qt * 8]);
                    asm volatile(
                        "ldmatrix.sync.aligned.m8n8.x2.trans.shared.b16 {%0,%1}, [%2];"
                        : "=r"(bfr[kt][qt][0]), "=r"(bfr[kt][qt][1]) : "r"(addr));
                }
            #pragma unroll
            for (int ct = 0; ct < 2; ct++) {
                unsigned af[2][4];
                #pragma unroll
                for (int kt = 0; kt < 2; kt++) {
                    const unsigned addr = su32(
                        &sVh[w * 32 + ct * 16 + (lane & 15)][kt * 16 + (lane >> 4) * 8]);
                    asm volatile(
                        "ldmatrix.sync.aligned.m8n8.x4.shared.b16 {%0,%1,%2,%3}, [%4];"
                        : "=r"(af[kt][0]), "=r"(af[kt][1]),
                          "=r"(af[kt][2]), "=r"(af[kt][3]) : "r"(addr));
                }
                #pragma unroll
                for (int qt = 0; qt < 2; qt++)
                    #pragma unroll
                    for (int kt = 0; kt < 2; kt++)
                        asm volatile(
                            "mma.sync.aligned.m16n8k16.row.col.f32.f16.f16.f32 "
                            "{%0,%1,%2,%3}, {%4,%5,%6,%7}, {%8,%9}, {%0,%1,%2,%3};"
                            : "+f"(d[ct][qt][0]), "+f"(d[ct][qt][1]),
                              "+f"(d[ct][qt][2]), "+f"(d[ct][qt][3])
                            : "r"(af[kt][0]), "r"(af[kt][1]),
                              "r"(af[kt][2]), "r"(af[kt][3]),
                              "r"(bfr[kt][qt][0]), "r"(bfr[kt][qt][1]));
            }
        }
    }

    // ---- epilogue: atomicAdd k-partials (out zeroed by proj_kernel) ----
    const int gid = lane >> 2;       // D row within tile
    const int tig = lane & 3;        // D col pair
    #pragma unroll
    for (int ct = 0; ct < 2; ct++)
        #pragma unroll
        for (int qt = 0; qt < 2; qt++) {
            const int c_r = w * 32 + ct * 16 + gid;
            const int q_c = q0 + qt * 8 + tig * 2;
            float* op = out + ((size_t)(b * CV_ + c_r)) * N_ + q_c;
            atomicAdd(op,              d[ct][qt][0]);
            atomicAdd(op + 1,          d[ct][qt][1]);
            atomicAdd(op + 8 * N_,     d[ct][qt][2]);
            atomicAdd(op + 8 * N_ + 1, d[ct][qt][3]);
        }
}

// ============================================================================
extern "C" void kernel_launch(void* const* d_in, const int* in_sizes, int n_in,
                              void* d_out, int out_size)
{
    const float* key   = (const float*)d_in[0];
    const float* query = (const float*)d_in[1];
    const float* value = (const float*)d_in[2];
    const float* Wk    = (const float*)d_in[3];
    const float* bk    = (const float*)d_in[4];
    const float* Wq    = (const float*)d_in[5];
    const float* bq    = (const float*)d_in[6];
    const float* wf    = (const float*)d_in[7];
    const float* bf    = (const float*)d_in[8];
    float* out = (float*)d_out;

    static int attr_set = 0;
    if (!attr_set) {
        cudaFuncSetAttribute(proj_kernel,
                             cudaFuncAttributeMaxDynamicSharedMemorySize,
                             PROJ_SMEM_BYTES);
        attr_set = 1;
    }

    proj_kernel<<<dim3(N_ / 32, B_, 3), 512, PROJ_SMEM_BYTES>>>(
        key, query, value, Wk, bk, Wq, bq, (float4*)out);
    fused_kernel<<<dim3(N_ / 16, KSPLIT, B_), 256>>>(wf, bf, out);
}

// round 14
// speedup vs baseline: 1.3826x; 1.0052x over previous
#include <cuda_runtime.h>
#include <cuda_fp16.h>

#define B_     4
#define CIN    256
#define CO_    64
#define N_     576   // 24*24
#define CV_    256
#define KSPLIT 6
#define CHUNKS 3     // 3 chunks of 32 k per split (6*3*32 = 576)

// Scratch (device globals — no allocation allowed)
__device__ unsigned g_kph[B_ * N_ * 32];   // (B, Nk, 32) half2 pairs over c
__device__ unsigned g_qph[B_ * N_ * 32];   // (B, Nq, 32)
__device__ __half   g_vh[B_ * CV_ * N_];   // fp16 copy of value

// ---------- packed helpers ----------
__device__ __forceinline__ unsigned long long pack2(float lo, float hi) {
    unsigned long long r;
    asm("mov.b64 %0, {%1, %2};" : "=l"(r) : "f"(lo), "f"(hi));
    return r;
}
__device__ __forceinline__ void unpack2(unsigned long long v, float& lo, float& hi) {
    asm("mov.b64 {%0, %1}, %2;" : "=f"(lo), "=f"(hi) : "l"(v));
}
__device__ __forceinline__ unsigned long long ffma2(unsigned long long a,
                                                    unsigned long long b,
                                                    unsigned long long c) {
    unsigned long long d;
    asm("fma.rn.f32x2 %0, %1, %2, %3;" : "=l"(d) : "l"(a), "l"(b), "l"(c));
    return d;
}
__device__ __forceinline__ float tanhfast(float x) {
    float y;
    asm("tanh.approx.f32 %0, %1;" : "=f"(y) : "f"(x));
    return y;
}
__device__ __forceinline__ unsigned tanh_h2(unsigned x) {
    unsigned y;
    asm("tanh.approx.f16x2 %0, %1;" : "=r"(y) : "r"(x));
    return y;
}
__device__ __forceinline__ __half2 u2h(unsigned u) { return *(__half2*)&u; }
__device__ __forceinline__ unsigned h2u(__half2 h) { return *(unsigned*)&h; }
__device__ __forceinline__ unsigned su32(const void* p) {
    return (unsigned)__cvta_generic_to_shared(p);
}

// ============================================================================
// Kernel A: kind 0/1: projections -> half2 (+ kind-0 zero-inits d_out).
//           kind 2: convert V -> fp16 (g_vh).
// grid (18, B, 3), 512 thr, __launch_bounds__(512,1).
// ============================================================================
#define PROJ_SMEM_BYTES ((256 * 32 + 256 * 66) * 4)

__global__ void __launch_bounds__(512, 1) proj_kernel(
    const float* __restrict__ key, const float* __restrict__ query,
    const float* __restrict__ value,
    const float* __restrict__ Wk,  const float* __restrict__ bk,
    const float* __restrict__ Wq,  const float* __restrict__ bq,
    float4* __restrict__ out_zero)
{
    const int kind = blockIdx.z;
    const int b  = blockIdx.y;
    const int n0 = blockIdx.x * 32;
    const int t  = threadIdx.x;

    if (kind == 2) {   // ---- V -> fp16 ----
        #pragma unroll
        for (int i = 0; i < 16; i++) {
            const int idx = i * 512 + t;          // 0..8191 = 256c x 32n
            const int c = idx >> 5;
            const int n = n0 + (idx & 31);
            g_vh[((size_t)(b * CV_ + c)) * N_ + n] =
                __float2half_rn(value[((size_t)(b * CV_ + c)) * N_ + n]);
        }
        return;
    }

    extern __shared__ float smem[];
    float (*sX)[32] = (float (*)[32])smem;               // [256 ch][32 n]
    float (*sW)[66] = (float (*)[66])(smem + 256 * 32);  // [256 ch][64 c]

    const float* X    = kind ? query : key;    // (B, CIN, N)
    const float* W    = kind ? Wq    : Wk;     // (CO, CIN)
    const float* bias = kind ? bq    : bk;
    unsigned* outp    = kind ? g_qph : g_kph;  // (B, N, 32) half2

    // ---- zero d_out (kind-0 blocks; 72 blocks x 512 thr x 4 float4) ----
    if (kind == 0) {
        const int idx = (b * 18 + blockIdx.x) * 512 + t;   // 0..36863
        #pragma unroll
        for (int i = 0; i < 4; i++)
            out_zero[i * 36864 + idx] = make_float4(0.f, 0.f, 0.f, 0.f);
    }

    {   // stage X: 256ch x 32n as float4 (coalesced)
        const int n4  = (t & 7) * 4;
        const int chb = t >> 3;                  // 0..63
        #pragma unroll
        for (int i = 0; i < 4; i++) {
            const int ch = chb + i * 64;
            *(float4*)&sX[ch][n4] =
                *(const float4*)&X[((size_t)(b * CIN + ch)) * N_ + n0 + n4];
        }
    }
    {   // stage W transposed: sW[ch][c]
        const int ch = t & 255;
        const int cb = (t >> 8) * 32;            // 0 or 32
        #pragma unroll 8
        for (int j = 0; j < 32; j++) {
            const int cr = cb + j;
            sW[ch][cr] = W[cr * CIN + ch];
        }
    }
    __syncthreads();

    const int ng = t & 15;           // n = 2*ng, 2*ng+1
    const int c  = (t >> 4) * 2;     // c, c+1

    unsigned long long a0 = 0ull, a1 = 0ull;

    for (int ch0 = 0; ch0 < CIN; ch0 += 8) {
        unsigned long long xps[8];
        float2 ws[8];
        #pragma unroll
        for (int i = 0; i < 8; i++) {
            xps[i] = *(const unsigned long long*)&sX[ch0 + i][ng * 2];
            ws[i]  = *(const float2*)&sW[ch0 + i][c];
        }
        #pragma unroll
        for (int i = 0; i < 8; i++) {
            a0 = ffma2(xps[i], pack2(ws[i].x, ws[i].x), a0);
            a1 = ffma2(xps[i], pack2(ws[i].y, ws[i].y), a1);
        }
    }

    const float bv0 = bias[c];
    const float bv1 = bias[c + 1];
    float c0n0, c0n1, c1n0, c1n1;
    unpack2(a0, c0n0, c0n1);
    unpack2(a1, c1n0, c1n1);

    const int n  = n0 + ng * 2;
    const int cc = c >> 1;
    outp[((size_t)b * N_ + n + 0) * 32 + cc] =
        h2u(__floats2half2_rn(c0n0 + bv0, c1n0 + bv1));
    outp[((size_t)b * N_ + n + 1) * 32 + cc] =
        h2u(__floats2half2_rn(c0n1 + bv0, c1n1 + bv1));
}

// ============================================================================
// Kernel B (FUSED v7 = v6 + occupancy 4): block = (16 q, 96 k-range, b),
// grid (36, 6, 4) = 864 blocks, 256 thr, __launch_bounds__(256,4) -> 64 regs,
// 4 resident blocks/SM so the barrier-locked attn(MUFU) / mma(tensor) phases
// interleave across blocks. Structure identical to v6 otherwise.
// ============================================================================
__global__ void __launch_bounds__(256, 4) fused_kernel(
    const float* __restrict__ wf, const float* __restrict__ bfp,
    float* __restrict__ out)
{
    __shared__ unsigned sqh[16][34];                 // q tile half2 pairs
    __shared__ unsigned swh[32];
    __shared__ unsigned skh[32][34];                 // current k chunk (half2)
    __shared__ __align__(16) __half sAh[32][24];     // attn fp16 [k][q], 48B rows
    __shared__ __align__(16) __half sVh[256][40];    // V fp16 [c][k], 80B rows

    const int b  = blockIdx.z;
    const int q0 = blockIdx.x * 16;
    const int kbase = blockIdx.y * (CHUNKS * 32);
    const int t  = threadIdx.x;
    const int lane = t & 31;
    const int w    = t >> 5;

    // ---- stage q tile (16 x 32 uint) + wf (once) ----
    {
        const int r = t >> 4;              // 0..15
        const int u = (t & 15) * 2;
        *(uint2*)&sqh[r][u] =
            *(const uint2*)&g_qph[((size_t)b * N_ + q0 + r) * 32 + u];
    }
    if (t < 32) {
        const float2 wv = *(const float2*)&wf[t * 2];
        swh[t] = h2u(__floats2half2_rn(wv.x, wv.y));
    }
    const float bf = __ldg(bfp);

    // attn mapping: scores (ka, qa) and (ka, qa+8)
    const int ka = lane;
    const int qa = w;                      // 0..7

    // mma accumulators: warp owns c = w*32..w*32+31 (2 c-tiles), 2 q-tiles
    float d[2][2][4];
    #pragma unroll
    for (int ct = 0; ct < 2; ct++)
        #pragma unroll
        for (int qt = 0; qt < 2; qt++)
            #pragma unroll
            for (int i = 0; i < 4; i++) d[ct][qt][i] = 0.f;

    for (int ch = 0; ch < CHUNKS; ch++) {
        const int k0 = kbase + ch * 32;
        __syncthreads();   // previous mma reads done: skh/sVh/sAh reusable

        // ---- stage skh (32x32 uint) ----
        {
            const int kk = t >> 3;
            const int u4 = (t & 7) * 4;
            const uint4 v = *(const uint4*)&g_kph[((size_t)b * N_ + k0 + kk) * 32 + u4];
            *(uint2*)&skh[kk][u4]     = make_uint2(v.x, v.y);
            *(uint2*)&skh[kk][u4 + 2] = make_uint2(v.z, v.w);
        }
        // ---- stage sVh: 256c x 32k fp16 (uint4 = 8 halves, coalesced) ----
        {
            const __half* vb = g_vh + ((size_t)b * CV_) * N_ + k0;
            #pragma unroll
            for (int i = 0; i < 4; i++) {
                const int idx = i * 256 + t;     // 0..1023 uint4
                const int c   = idx >> 2;
                const int kq  = (idx & 3) * 8;
                *(uint4*)&sVh[c][kq] = *(const uint4*)(vb + (size_t)c * N_ + kq);
            }
        }
        __syncthreads();

        // ---- attn: 2 scores per thread -> sAh fp16 ----
        {
            __half2 aeA = __float2half2_rn(0.f), aoA = aeA;
            __half2 aeB = aeA, aoB = aeA;
            const unsigned* __restrict__ krow  = skh[ka];
            const unsigned* __restrict__ qrowA = sqh[qa];
            const unsigned* __restrict__ qrowB = sqh[qa + 8];
            #pragma unroll 8
            for (int cc = 0; cc < 32; cc += 2) {
                const uint2 kv = *(const uint2*)&krow[cc];
                const uint2 wv = *(const uint2*)&swh[cc];
                const uint2 qA = *(const uint2*)&qrowA[cc];
                const uint2 qB = *(const uint2*)&qrowB[cc];
                const unsigned tA0 = tanh_h2(h2u(__hadd2(u2h(kv.x), u2h(qA.x))));
                const unsigned tA1 = tanh_h2(h2u(__hadd2(u2h(kv.y), u2h(qA.y))));
                const unsigned tB0 = tanh_h2(h2u(__hadd2(u2h(kv.x), u2h(qB.x))));
                const unsigned tB1 = tanh_h2(h2u(__hadd2(u2h(kv.y), u2h(qB.y))));
                aeA = __hfma2(u2h(tA0), u2h(wv.x), aeA);
                aoA = __hfma2(u2h(tA1), u2h(wv.y), aoA);
                aeB = __hfma2(u2h(tB0), u2h(wv.x), aeB);
                aoB = __hfma2(u2h(tB1), u2h(wv.y), aoB);
            }
            const float2 feA = __half22float2(aeA);
            const float2 foA = __half22float2(aoA);
            const float2 feB = __half22float2(aeB);
            const float2 foB = __half22float2(aoB);
            const float sAv = bf + ((feA.x + feA.y) + (foA.x + foA.y));
            const float sBv = bf + ((feB.x + feB.y) + (foB.x + foB.y));
            sAh[ka][qa]     = __float2half_rn(fmaf(0.5f, tanhfast(0.5f * sAv), 0.5f));
            sAh[ka][qa + 8] = __float2half_rn(fmaf(0.5f, tanhfast(0.5f * sBv), 0.5f));
        }
        __syncthreads();

        // ---- tensor-core contract: D += V[c,k] * A[k,q] ----
        {
            // B frags: [ktile][qtile], ldmatrix.x2.trans on sAh rows [k][q]
            unsigned bfr[2][2][2];
            #pragma unroll
            for (int kt = 0; kt < 2; kt++)
                #pragma unroll
                for (int qt = 0; qt < 2; qt++) {
                    const unsigned addr = su32(&sAh[kt * 16 + (lane & 15)][qt * 8]);
                    asm volatile(
                        "ldmatrix.sync.aligned.m8n8.x2.trans.shared.b16 {%0,%1}, [%2];"
                        : "=r"(bfr[kt][qt][0]), "=r"(bfr[kt][qt][1]) : "r"(addr));
                }
            #pragma unroll
            for (int ct = 0; ct < 2; ct++) {
                unsigned af[2][4];
                #pragma unroll
                for (int kt = 0; kt < 2; kt++) {
                    const unsigned addr = su32(
                        &sVh[w * 32 + ct * 16 + (lane & 15)][kt * 16 + (lane >> 4) * 8]);
                    asm volatile(
                        "ldmatrix.sync.aligned.m8n8.x4.shared.b16 {%0,%1,%2,%3}, [%4];"
                        : "=r"(af[kt][0]), "=r"(af[kt][1]),
                          "=r"(af[kt][2]), "=r"(af[kt][3]) : "r"(addr));
                }
                #pragma unroll
                for (int qt = 0; qt < 2; qt++)
                    #pragma unroll
                    for (int kt = 0; kt < 2; kt++)
                        asm volatile(
                            "mma.sync.aligned.m16n8k16.row.col.f32.f16.f16.f32 "
                            "{%0,%1,%2,%3}, {%4,%5,%6,%7}, {%8,%9}, {%0,%1,%2,%3};"
                            : "+f"(d[ct][qt][0]), "+f"(d[ct][qt][1]),
                              "+f"(d[ct][qt][2]), "+f"(d[ct][qt][3])
                            : "r"(af[kt][0]), "r"(af[kt][1]),
                              "r"(af[kt][2]), "r"(af[kt][3]),
                              "r"(bfr[kt][qt][0]), "r"(bfr[kt][qt][1]));
            }
        }
    }

    // ---- epilogue: atomicAdd k-partials (out zeroed by proj_kernel) ----
    const int gid = lane >> 2;       // D row within tile
    const int tig = lane & 3;        // D col pair
    #pragma unroll
    for (int ct = 0; ct < 2; ct++)
        #pragma unroll
        for (int qt = 0; qt < 2; qt++) {
            const int c_r = w * 32 + ct * 16 + gid;
            const int q_c = q0 + qt * 8 + tig * 2;
            float* op = out + ((size_t)(b * CV_ + c_r)) * N_ + q_c;
            atomicAdd(op,              d[ct][qt][0]);
            atomicAdd(op + 1,          d[ct][qt][1]);
            atomicAdd(op + 8 * N_,     d[ct][qt][2]);
            atomicAdd(op + 8 * N_ + 1, d[ct][qt][3]);
        }
}

// ============================================================================
extern "C" void kernel_launch(void* const* d_in, const int* in_sizes, int n_in,
                              void* d_out, int out_size)
{
    const float* key   = (const float*)d_in[0];
    const float* query = (const float*)d_in[1];
    const float* value = (const float*)d_in[2];
    const float* Wk    = (const float*)d_in[3];
    const float* bk    = (const float*)d_in[4];
    const float* Wq    = (const float*)d_in[5];
    const float* bq    = (const float*)d_in[6];
    const float* wf    = (const float*)d_in[7];
    const float* bf    = (const float*)d_in[8];
    float* out = (float*)d_out;

    static int attr_set = 0;
    if (!attr_set) {
        cudaFuncSetAttribute(proj_kernel,
                             cudaFuncAttributeMaxDynamicSharedMemorySize,
                             PROJ_SMEM_BYTES);
        attr_set = 1;
    }

    proj_kernel<<<dim3(N_ / 32, B_, 3), 512, PROJ_SMEM_BYTES>>>(
        key, query, value, Wk, bk, Wq, bq, (float4*)out);
    fused_kernel<<<dim3(N_ / 16, KSPLIT, B_), 256>>>(wf, bf, out);
}

// round 15
// speedup vs baseline: 1.4421x; 1.0430x over previous
#include <cuda_runtime.h>
#include <cuda_fp16.h>

#define B_     4
#define CIN    256
#define CO_    64
#define N_     576   // 24*24
#define CV_    256
#define KSPLIT 6
#define CHUNKS 3     // 3 chunks of 32 k per split (6*3*32 = 576)

// Scratch (device globals — no allocation allowed)
__device__ unsigned g_kph[B_ * N_ * 32];   // (B, Nk, 32) half2 pairs over c
__device__ unsigned g_qph[B_ * N_ * 32];   // (B, Nq, 32)
__device__ __half   g_vh[B_ * CV_ * N_];   // fp16 copy of value

// ---------- packed helpers ----------
__device__ __forceinline__ unsigned long long pack2(float lo, float hi) {
    unsigned long long r;
    asm("mov.b64 %0, {%1, %2};" : "=l"(r) : "f"(lo), "f"(hi));
    return r;
}
__device__ __forceinline__ void unpack2(unsigned long long v, float& lo, float& hi) {
    asm("mov.b64 {%0, %1}, %2;" : "=f"(lo), "=f"(hi) : "l"(v));
}
__device__ __forceinline__ unsigned long long ffma2(unsigned long long a,
                                                    unsigned long long b,
                                                    unsigned long long c) {
    unsigned long long d;
    asm("fma.rn.f32x2 %0, %1, %2, %3;" : "=l"(d) : "l"(a), "l"(b), "l"(c));
    return d;
}
__device__ __forceinline__ float tanhfast(float x) {
    float y;
    asm("tanh.approx.f32 %0, %1;" : "=f"(y) : "f"(x));
    return y;
}
__device__ __forceinline__ unsigned tanh_h2(unsigned x) {
    unsigned y;
    asm("tanh.approx.f16x2 %0, %1;" : "=r"(y) : "r"(x));
    return y;
}
__device__ __forceinline__ __half2 u2h(unsigned u) { return *(__half2*)&u; }
__device__ __forceinline__ unsigned h2u(__half2 h) { return *(unsigned*)&h; }
__device__ __forceinline__ unsigned su32(const void* p) {
    return (unsigned)__cvta_generic_to_shared(p);
}

// ============================================================================
// Kernel A: kind 0/1: projections -> half2 (+ kind-0 zero-inits d_out).
//           kind 2: convert V -> fp16 (g_vh).
// grid (18, B, 3), 512 thr, __launch_bounds__(512,1).
// ============================================================================
#define PROJ_SMEM_BYTES ((256 * 32 + 256 * 66) * 4)

__global__ void __launch_bounds__(512, 1) proj_kernel(
    const float* __restrict__ key, const float* __restrict__ query,
    const float* __restrict__ value,
    const float* __restrict__ Wk,  const float* __restrict__ bk,
    const float* __restrict__ Wq,  const float* __restrict__ bq,
    float4* __restrict__ out_zero)
{
    const int kind = blockIdx.z;
    const int b  = blockIdx.y;
    const int n0 = blockIdx.x * 32;
    const int t  = threadIdx.x;

    if (kind == 2) {   // ---- V -> fp16 ----
        #pragma unroll
        for (int i = 0; i < 16; i++) {
            const int idx = i * 512 + t;          // 0..8191 = 256c x 32n
            const int c = idx >> 5;
            const int n = n0 + (idx & 31);
            g_vh[((size_t)(b * CV_ + c)) * N_ + n] =
                __float2half_rn(value[((size_t)(b * CV_ + c)) * N_ + n]);
        }
        return;
    }

    extern __shared__ float smem[];
    float (*sX)[32] = (float (*)[32])smem;               // [256 ch][32 n]
    float (*sW)[66] = (float (*)[66])(smem + 256 * 32);  // [256 ch][64 c]

    const float* X    = kind ? query : key;    // (B, CIN, N)
    const float* W    = kind ? Wq    : Wk;     // (CO, CIN)
    const float* bias = kind ? bq    : bk;
    unsigned* outp    = kind ? g_qph : g_kph;  // (B, N, 32) half2

    // ---- zero d_out (kind-0 blocks; 72 blocks x 512 thr x 4 float4) ----
    if (kind == 0) {
        const int idx = (b * 18 + blockIdx.x) * 512 + t;   // 0..36863
        #pragma unroll
        for (int i = 0; i < 4; i++)
            out_zero[i * 36864 + idx] = make_float4(0.f, 0.f, 0.f, 0.f);
    }

    {   // stage X: 256ch x 32n as float4 (coalesced)
        const int n4  = (t & 7) * 4;
        const int chb = t >> 3;                  // 0..63
        #pragma unroll
        for (int i = 0; i < 4; i++) {
            const int ch = chb + i * 64;
            *(float4*)&sX[ch][n4] =
                *(const float4*)&X[((size_t)(b * CIN + ch)) * N_ + n0 + n4];
        }
    }
    {   // stage W transposed: sW[ch][c]
        const int ch = t & 255;
        const int cb = (t >> 8) * 32;            // 0 or 32
        #pragma unroll 8
        for (int j = 0; j < 32; j++) {
            const int cr = cb + j;
            sW[ch][cr] = W[cr * CIN + ch];
        }
    }
    __syncthreads();

    const int ng = t & 15;           // n = 2*ng, 2*ng+1
    const int c  = (t >> 4) * 2;     // c, c+1

    unsigned long long a0 = 0ull, a1 = 0ull;

    for (int ch0 = 0; ch0 < CIN; ch0 += 8) {
        unsigned long long xps[8];
        float2 ws[8];
        #pragma unroll
        for (int i = 0; i < 8; i++) {
            xps[i] = *(const unsigned long long*)&sX[ch0 + i][ng * 2];
            ws[i]  = *(const float2*)&sW[ch0 + i][c];
        }
        #pragma unroll
        for (int i = 0; i < 8; i++) {
            a0 = ffma2(xps[i], pack2(ws[i].x, ws[i].x), a0);
            a1 = ffma2(xps[i], pack2(ws[i].y, ws[i].y), a1);
        }
    }

    const float bv0 = bias[c];
    const float bv1 = bias[c + 1];
    float c0n0, c0n1, c1n0, c1n1;
    unpack2(a0, c0n0, c0n1);
    unpack2(a1, c1n0, c1n1);

    const int n  = n0 + ng * 2;
    const int cc = c >> 1;
    outp[((size_t)b * N_ + n + 0) * 32 + cc] =
        h2u(__floats2half2_rn(c0n0 + bv0, c1n0 + bv1));
    outp[((size_t)b * N_ + n + 1) * 32 + cc] =
        h2u(__floats2half2_rn(c0n1 + bv0, c1n1 + bv1));
}

// ============================================================================
// Kernel B (FUSED v8 = v7 with q-tile 32): block = (32 q, 96 k-range, b),
// grid (18, 6, 4) = 432 blocks, 256 thr, __launch_bounds__(256,4).
// Staging (skh/sVh), ldmatrix-A and barriers amortized over 2x the q's.
// attn: 4 scores/thread (q = qa + 8i). mma: 2 c-tiles x 4 q-tiles x 2 k-steps.
// ============================================================================
__global__ void __launch_bounds__(256, 4) fused_kernel(
    const float* __restrict__ wf, const float* __restrict__ bfp,
    float* __restrict__ out)
{
    __shared__ unsigned sqh[32][34];                 // q tile half2 pairs
    __shared__ unsigned swh[32];
    __shared__ unsigned skh[32][34];                 // current k chunk (half2)
    __shared__ __align__(16) __half sAh[32][40];     // attn fp16 [k][q], 80B rows
    __shared__ __align__(16) __half sVh[256][40];    // V fp16 [c][k], 80B rows

    const int b  = blockIdx.z;
    const int q0 = blockIdx.x * 32;
    const int kbase = blockIdx.y * (CHUNKS * 32);
    const int t  = threadIdx.x;
    const int lane = t & 31;
    const int w    = t >> 5;

    // ---- stage q tile (32 x 32 uint = 512 uint2) + wf (once) ----
    #pragma unroll
    for (int j = 0; j < 2; j++) {
        const int idx = t + j * 256;
        const int r = idx >> 4;              // 0..31
        const int u = (idx & 15) * 2;
        *(uint2*)&sqh[r][u] =
            *(const uint2*)&g_qph[((size_t)b * N_ + q0 + r) * 32 + u];
    }
    if (t < 32) {
        const float2 wv = *(const float2*)&wf[t * 2];
        swh[t] = h2u(__floats2half2_rn(wv.x, wv.y));
    }
    const float bf = __ldg(bfp);

    // attn mapping: scores (ka, qa + 8i), i = 0..3
    const int ka = lane;
    const int qa = w;                      // 0..7

    // mma accumulators: warp owns c = w*32..w*32+31 (2 c-tiles), 4 q-tiles
    float d[2][4][4];
    #pragma unroll
    for (int ct = 0; ct < 2; ct++)
        #pragma unroll
        for (int qt = 0; qt < 4; qt++)
            #pragma unroll
            for (int i = 0; i < 4; i++) d[ct][qt][i] = 0.f;

    for (int ch = 0; ch < CHUNKS; ch++) {
        const int k0 = kbase + ch * 32;
        __syncthreads();   // previous mma reads done: skh/sVh/sAh reusable

        // ---- stage skh (32x32 uint) ----
        {
            const int kk = t >> 3;
            const int u4 = (t & 7) * 4;
            const uint4 v = *(const uint4*)&g_kph[((size_t)b * N_ + k0 + kk) * 32 + u4];
            *(uint2*)&skh[kk][u4]     = make_uint2(v.x, v.y);
            *(uint2*)&skh[kk][u4 + 2] = make_uint2(v.z, v.w);
        }
        // ---- stage sVh: 256c x 32k fp16 (uint4 = 8 halves, coalesced) ----
        {
            const __half* vb = g_vh + ((size_t)b * CV_) * N_ + k0;
            #pragma unroll
            for (int i = 0; i < 4; i++) {
                const int idx = i * 256 + t;     // 0..1023 uint4
                const int c   = idx >> 2;
                const int kq  = (idx & 3) * 8;
                *(uint4*)&sVh[c][kq] = *(const uint4*)(vb + (size_t)c * N_ + kq);
            }
        }
        __syncthreads();

        // ---- attn: 4 scores per thread -> sAh fp16 ----
        {
            __half2 ae[4], ao[4];
            #pragma unroll
            for (int i = 0; i < 4; i++) { ae[i] = __float2half2_rn(0.f); ao[i] = ae[i]; }
            const unsigned* __restrict__ krow = skh[ka];
            #pragma unroll 8
            for (int cc = 0; cc < 32; cc += 2) {
                const uint2 kv = *(const uint2*)&krow[cc];
                const uint2 wv = *(const uint2*)&swh[cc];
                #pragma unroll
                for (int i = 0; i < 4; i++) {
                    const uint2 qv = *(const uint2*)&sqh[qa + 8 * i][cc];
                    const unsigned t0 = tanh_h2(h2u(__hadd2(u2h(kv.x), u2h(qv.x))));
                    const unsigned t1 = tanh_h2(h2u(__hadd2(u2h(kv.y), u2h(qv.y))));
                    ae[i] = __hfma2(u2h(t0), u2h(wv.x), ae[i]);
                    ao[i] = __hfma2(u2h(t1), u2h(wv.y), ao[i]);
                }
            }
            #pragma unroll
            for (int i = 0; i < 4; i++) {
                const float2 fe = __half22float2(ae[i]);
                const float2 fo = __half22float2(ao[i]);
                const float s = bf + ((fe.x + fe.y) + (fo.x + fo.y));
                sAh[ka][qa + 8 * i] =
                    __float2half_rn(fmaf(0.5f, tanhfast(0.5f * s), 0.5f));
            }
        }
        __syncthreads();

        // ---- tensor-core contract: D += V[c,k] * A[k,q] ----
        #pragma unroll
        for (int ct = 0; ct < 2; ct++) {
            unsigned af[2][4];
            #pragma unroll
            for (int kt = 0; kt < 2; kt++) {
                const unsigned addr = su32(
                    &sVh[w * 32 + ct * 16 + (lane & 15)][kt * 16 + (lane >> 4) * 8]);
                asm volatile(
                    "ldmatrix.sync.aligned.m8n8.x4.shared.b16 {%0,%1,%2,%3}, [%4];"
                    : "=r"(af[kt][0]), "=r"(af[kt][1]),
                      "=r"(af[kt][2]), "=r"(af[kt][3]) : "r"(addr));
            }
            #pragma unroll
            for (int qt = 0; qt < 4; qt++) {
                #pragma unroll
                for (int kt = 0; kt < 2; kt++) {
                    unsigned b0, b1;
                    const unsigned addr = su32(&sAh[kt * 16 + (lane & 15)][qt * 8]);
                    asm volatile(
                        "ldmatrix.sync.aligned.m8n8.x2.trans.shared.b16 {%0,%1}, [%2];"
                        : "=r"(b0), "=r"(b1) : "r"(addr));
                    asm volatile(
                        "mma.sync.aligned.m16n8k16.row.col.f32.f16.f16.f32 "
                        "{%0,%1,%2,%3}, {%4,%5,%6,%7}, {%8,%9}, {%0,%1,%2,%3};"
                        : "+f"(d[ct][qt][0]), "+f"(d[ct][qt][1]),
                          "+f"(d[ct][qt][2]), "+f"(d[ct][qt][3])
                        : "r"(af[kt][0]), "r"(af[kt][1]),
                          "r"(af[kt][2]), "r"(af[kt][3]),
                          "r"(b0), "r"(b1));
                }
            }
        }
    }

    // ---- epilogue: atomicAdd k-partials (out zeroed by proj_kernel) ----
    const int gid = lane >> 2;       // D row within tile
    const int tig = lane & 3;        // D col pair
    #pragma unroll
    for (int ct = 0; ct < 2; ct++)
        #pragma unroll
        for (int qt = 0; qt < 4; qt++) {
            const int c_r = w * 32 + ct * 16 + gid;
            const int q_c = q0 + qt * 8 + tig * 2;
            float* op = out + ((size_t)(b * CV_ + c_r)) * N_ + q_c;
            atomicAdd(op,              d[ct][qt][0]);
            atomicAdd(op + 1,          d[ct][qt][1]);
            atomicAdd(op + 8 * N_,     d[ct][qt][2]);
            atomicAdd(op + 8 * N_ + 1, d[ct][qt][3]);
        }
}

// ============================================================================
extern "C" void kernel_launch(void* const* d_in, const int* in_sizes, int n_in,
                              void* d_out, int out_size)
{
    const float* key   = (const float*)d_in[0];
    const float* query = (const float*)d_in[1];
    const float* value = (const float*)d_in[2];
    const float* Wk    = (const float*)d_in[3];
    const float* bk    = (const float*)d_in[4];
    const float* Wq    = (const float*)d_in[5];
    const float* bq    = (const float*)d_in[6];
    const float* wf    = (const float*)d_in[7];
    const float* bf    = (const float*)d_in[8];
    float* out = (float*)d_out;

    static int attr_set = 0;
    if (!attr_set) {
        cudaFuncSetAttribute(proj_kernel,
                             cudaFuncAttributeMaxDynamicSharedMemorySize,
                             PROJ_SMEM_BYTES);
        attr_set = 1;
    }

    proj_kernel<<<dim3(N_ / 32, B_, 3), 512, PROJ_SMEM_BYTES>>>(
        key, query, value, Wk, bk, Wq, bq, (float4*)out);
    fused_kernel<<<dim3(N_ / 32, KSPLIT, B_), 256>>>(wf, bf, out);
}

// round 16
// speedup vs baseline: 1.4657x; 1.0164x over previous
#include <cuda_runtime.h>
#include <cuda_fp16.h>

#define B_     4
#define CIN    256
#define CO_    64
#define N_     576   // 24*24
#define CV_    256
#define KSPLIT 6
#define CHUNKS 3     // 3 chunks of 32 k per split (6*3*32 = 576)

// Scratch (device globals — no allocation allowed)
__device__ unsigned g_kph[B_ * N_ * 32];   // (B, Nk, 32) half2 pairs over c
__device__ unsigned g_qph[B_ * N_ * 32];   // (B, Nq, 32)
__device__ __half   g_vh[B_ * CV_ * N_];   // fp16 copy of value

// ---------- packed helpers ----------
__device__ __forceinline__ unsigned long long pack2(float lo, float hi) {
    unsigned long long r;
    asm("mov.b64 %0, {%1, %2};" : "=l"(r) : "f"(lo), "f"(hi));
    return r;
}
__device__ __forceinline__ void unpack2(unsigned long long v, float& lo, float& hi) {
    asm("mov.b64 {%0, %1}, %2;" : "=f"(lo), "=f"(hi) : "l"(v));
}
__device__ __forceinline__ unsigned long long ffma2(unsigned long long a,
                                                    unsigned long long b,
                                                    unsigned long long c) {
    unsigned long long d;
    asm("fma.rn.f32x2 %0, %1, %2, %3;" : "=l"(d) : "l"(a), "l"(b), "l"(c));
    return d;
}
__device__ __forceinline__ float tanhfast(float x) {
    float y;
    asm("tanh.approx.f32 %0, %1;" : "=f"(y) : "f"(x));
    return y;
}
__device__ __forceinline__ unsigned tanh_h2(unsigned x) {
    unsigned y;
    asm("tanh.approx.f16x2 %0, %1;" : "=r"(y) : "r"(x));
    return y;
}
__device__ __forceinline__ __half2 u2h(unsigned u) { return *(__half2*)&u; }
__device__ __forceinline__ unsigned h2u(__half2 h) { return *(unsigned*)&h; }
__device__ __forceinline__ unsigned su32(const void* p) {
    return (unsigned)__cvta_generic_to_shared(p);
}
__device__ __forceinline__ void cp16(unsigned dst, const void* src) {
    asm volatile("cp.async.cg.shared.global [%0], [%1], 16;" :: "r"(dst), "l"(src));
}
__device__ __forceinline__ void cp8(unsigned dst, const void* src) {
    asm volatile("cp.async.ca.shared.global [%0], [%1], 8;" :: "r"(dst), "l"(src));
}
__device__ __forceinline__ void cp_commit() {
    asm volatile("cp.async.commit_group;" ::: "memory");
}
__device__ __forceinline__ void cp_wait_all() {
    asm volatile("cp.async.wait_group 0;" ::: "memory");
}

// ============================================================================
// Kernel A: kind 0/1: projections -> half2 (+ kind-0 zero-inits d_out).
//           kind 2: convert V -> fp16 (g_vh).
// grid (18, B, 3), 512 thr, __launch_bounds__(512,1).
// ============================================================================
#define PROJ_SMEM_BYTES ((256 * 32 + 256 * 66) * 4)

__global__ void __launch_bounds__(512, 1) proj_kernel(
    const float* __restrict__ key, const float* __restrict__ query,
    const float* __restrict__ value,
    const float* __restrict__ Wk,  const float* __restrict__ bk,
    const float* __restrict__ Wq,  const float* __restrict__ bq,
    float4* __restrict__ out_zero)
{
    const int kind = blockIdx.z;
    const int b  = blockIdx.y;
    const int n0 = blockIdx.x * 32;
    const int t  = threadIdx.x;

    if (kind == 2) {   // ---- V -> fp16 ----
        #pragma unroll
        for (int i = 0; i < 16; i++) {
            const int idx = i * 512 + t;          // 0..8191 = 256c x 32n
            const int c = idx >> 5;
            const int n = n0 + (idx & 31);
            g_vh[((size_t)(b * CV_ + c)) * N_ + n] =
                __float2half_rn(value[((size_t)(b * CV_ + c)) * N_ + n]);
        }
        return;
    }

    extern __shared__ float smem[];
    float (*sX)[32] = (float (*)[32])smem;               // [256 ch][32 n]
    float (*sW)[66] = (float (*)[66])(smem + 256 * 32);  // [256 ch][64 c]

    const float* X    = kind ? query : key;    // (B, CIN, N)
    const float* W    = kind ? Wq    : Wk;     // (CO, CIN)
    const float* bias = kind ? bq    : bk;
    unsigned* outp    = kind ? g_qph : g_kph;  // (B, N, 32) half2

    // ---- zero d_out (kind-0 blocks; 72 blocks x 512 thr x 4 float4) ----
    if (kind == 0) {
        const int idx = (b * 18 + blockIdx.x) * 512 + t;   // 0..36863
        #pragma unroll
        for (int i = 0; i < 4; i++)
            out_zero[i * 36864 + idx] = make_float4(0.f, 0.f, 0.f, 0.f);
    }

    {   // stage X: 256ch x 32n as float4 (coalesced)
        const int n4  = (t & 7) * 4;
        const int chb = t >> 3;                  // 0..63
        #pragma unroll
        for (int i = 0; i < 4; i++) {
            const int ch = chb + i * 64;
            *(float4*)&sX[ch][n4] =
                *(const float4*)&X[((size_t)(b * CIN + ch)) * N_ + n0 + n4];
        }
    }
    {   // stage W transposed: sW[ch][c]
        const int ch = t & 255;
        const int cb = (t >> 8) * 32;            // 0 or 32
        #pragma unroll 8
        for (int j = 0; j < 32; j++) {
            const int cr = cb + j;
            sW[ch][cr] = W[cr * CIN + ch];
        }
    }
    __syncthreads();

    const int ng = t & 15;           // n = 2*ng, 2*ng+1
    const int c  = (t >> 4) * 2;     // c, c+1

    unsigned long long a0 = 0ull, a1 = 0ull;

    for (int ch0 = 0; ch0 < CIN; ch0 += 8) {
        unsigned long long xps[8];
        float2 ws[8];
        #pragma unroll
        for (int i = 0; i < 8; i++) {
            xps[i] = *(const unsigned long long*)&sX[ch0 + i][ng * 2];
            ws[i]  = *(const float2*)&sW[ch0 + i][c];
        }
        #pragma unroll
        for (int i = 0; i < 8; i++) {
            a0 = ffma2(xps[i], pack2(ws[i].x, ws[i].x), a0);
            a1 = ffma2(xps[i], pack2(ws[i].y, ws[i].y), a1);
        }
    }

    const float bv0 = bias[c];
    const float bv1 = bias[c + 1];
    float c0n0, c0n1, c1n0, c1n1;
    unpack2(a0, c0n0, c0n1);
    unpack2(a1, c1n0, c1n1);

    const int n  = n0 + ng * 2;
    const int cc = c >> 1;
    outp[((size_t)b * N_ + n + 0) * 32 + cc] =
        h2u(__floats2half2_rn(c0n0 + bv0, c1n0 + bv1));
    outp[((size_t)b * N_ + n + 1) * 32 + cc] =
        h2u(__floats2half2_rn(c0n1 + bv0, c1n1 + bv1));
}

// ============================================================================
// Kernel B (FUSED v9 = v8 + cp.async double-buffered staging, 2 barriers/chunk)
// block = (32 q, 96 k-range, b), grid (18, 6, 4) = 432, 256 thr.
// Per chunk: [wait+bar] issue prefetch(ch+1) | attn(ch) -> sAh | [bar] | mma(ch).
// Staging latency spans a full attn+mma phase -> fully hidden.
// ============================================================================
__global__ void __launch_bounds__(256, 3) fused_kernel(
    const float* __restrict__ wf, const float* __restrict__ bfp,
    float* __restrict__ out)
{
    __shared__ unsigned sqh[32][34];                    // q tile half2 pairs
    __shared__ unsigned swh[32];
    __shared__ unsigned skh[2][32][34];                 // k chunk, double-buffered
    __shared__ __align__(16) __half sAh[32][40];        // attn fp16 [k][q]
    __shared__ __align__(16) __half sVh[2][256][40];    // V fp16 [c][k], dbl-buf

    const int b  = blockIdx.z;
    const int q0 = blockIdx.x * 32;
    const int kbase = blockIdx.y * (CHUNKS * 32);
    const int t  = threadIdx.x;
    const int lane = t & 31;
    const int w    = t >> 5;

    // ---- stage q tile (512 uint2) + wf (once) ----
    #pragma unroll
    for (int j = 0; j < 2; j++) {
        const int idx = t + j * 256;
        const int r = idx >> 4;              // 0..31
        const int u = (idx & 15) * 2;
        *(uint2*)&sqh[r][u] =
            *(const uint2*)&g_qph[((size_t)b * N_ + q0 + r) * 32 + u];
    }
    if (t < 32) {
        const float2 wv = *(const float2*)&wf[t * 2];
        swh[t] = h2u(__floats2half2_rn(wv.x, wv.y));
    }
    const float bf = __ldg(bfp);

    // staging source/dst precomputed
    //   sVh: 4 x cp16 per thread; skh: 2 x cp8 per thread
    const int vc  = t >> 2;                  // hmm: idx = i*256+t: c = idx>>2
    const __half* vbase = g_vh + ((size_t)b * CV_) * N_ + kbase;
    const unsigned* kbase_p = g_kph + ((size_t)b * N_ + kbase) * 32;

    // ---- prologue: prefetch chunk 0 ----
    {
        #pragma unroll
        for (int i = 0; i < 4; i++) {
            const int idx = i * 256 + t;     // 0..1023
            const int c   = idx >> 2;
            const int kq  = (idx & 3) * 8;
            cp16(su32(&sVh[0][c][kq]), vbase + (size_t)c * N_ + kq);
        }
        #pragma unroll
        for (int i = 0; i < 2; i++) {
            const int idx = i * 256 + t;     // 0..511 (8B units)
            const int kk  = idx >> 4;
            const int u   = (idx & 15) * 2;
            cp8(su32(&skh[0][kk][u]), kbase_p + kk * 32 + u);
        }
        cp_commit();
    }

    // attn mapping: scores (ka, qa + 8i), i = 0..3
    const int ka = lane;
    const int qa = w;                        // 0..7

    // mma accumulators: warp owns c = w*32..w*32+31 (2 c-tiles), 4 q-tiles
    float d[2][4][4];
    #pragma unroll
    for (int ct = 0; ct < 2; ct++)
        #pragma unroll
        for (int qt = 0; qt < 4; qt++)
            #pragma unroll
            for (int i = 0; i < 4; i++) d[ct][qt][i] = 0.f;

    for (int ch = 0; ch < CHUNKS; ch++) {
        const int buf = ch & 1;

        cp_wait_all();       // group(ch) complete (issued >= 1 phase ago)
        __syncthreads();     // data visible to all; all warps done mma(ch-1)

        // ---- prefetch chunk ch+1 into buf^1 (async; hidden under attn+mma) ----
        if (ch + 1 < CHUNKS) {
            const int koff = (ch + 1) * 32;
            #pragma unroll
            for (int i = 0; i < 4; i++) {
                const int idx = i * 256 + t;
                const int c   = idx >> 2;
                const int kq  = (idx & 3) * 8;
                cp16(su32(&sVh[buf ^ 1][c][kq]), vbase + (size_t)c * N_ + koff + kq);
            }
            #pragma unroll
            for (int i = 0; i < 2; i++) {
                const int idx = i * 256 + t;
                const int kk  = idx >> 4;
                const int u   = (idx & 15) * 2;
                cp8(su32(&skh[buf ^ 1][kk][u]), kbase_p + (koff + kk) * 32 + u);
            }
            cp_commit();
        }

        // ---- attn: 4 scores per thread -> sAh fp16 ----
        {
            __half2 ae[4], ao[4];
            #pragma unroll
            for (int i = 0; i < 4; i++) { ae[i] = __float2half2_rn(0.f); ao[i] = ae[i]; }
            const unsigned* __restrict__ krow = skh[buf][ka];
            #pragma unroll 8
            for (int cc = 0; cc < 32; cc += 2) {
                const uint2 kv = *(const uint2*)&krow[cc];
                const uint2 wv = *(const uint2*)&swh[cc];
                #pragma unroll
                for (int i = 0; i < 4; i++) {
                    const uint2 qv = *(const uint2*)&sqh[qa + 8 * i][cc];
                    const unsigned t0 = tanh_h2(h2u(__hadd2(u2h(kv.x), u2h(qv.x))));
                    const unsigned t1 = tanh_h2(h2u(__hadd2(u2h(kv.y), u2h(qv.y))));
                    ae[i] = __hfma2(u2h(t0), u2h(wv.x), ae[i]);
                    ao[i] = __hfma2(u2h(t1), u2h(wv.y), ao[i]);
                }
            }
            #pragma unroll
            for (int i = 0; i < 4; i++) {
                const float2 fe = __half22float2(ae[i]);
                const float2 fo = __half22float2(ao[i]);
                const float s = bf + ((fe.x + fe.y) + (fo.x + fo.y));
                sAh[ka][qa + 8 * i] =
                    __float2half_rn(fmaf(0.5f, tanhfast(0.5f * s), 0.5f));
            }
        }
        __syncthreads();     // sAh complete

        // ---- tensor-core contract: D += V[c,k] * A[k,q] ----
        #pragma unroll
        for (int ct = 0; ct < 2; ct++) {
            unsigned af[2][4];
            #pragma unroll
            for (int kt = 0; kt < 2; kt++) {
                const unsigned addr = su32(
                    &sVh[buf][w * 32 + ct * 16 + (lane & 15)][kt * 16 + (lane >> 4) * 8]);
                asm volatile(
                    "ldmatrix.sync.aligned.m8n8.x4.shared.b16 {%0,%1,%2,%3}, [%4];"
                    : "=r"(af[kt][0]), "=r"(af[kt][1]),
                      "=r"(af[kt][2]), "=r"(af[kt][3]) : "r"(addr));
            }
            #pragma unroll
            for (int qt = 0; qt < 4; qt++) {
                #pragma unroll
                for (int kt = 0; kt < 2; kt++) {
                    unsigned b0, b1;
                    const unsigned addr = su32(&sAh[kt * 16 + (lane & 15)][qt * 8]);
                    asm volatile(
                        "ldmatrix.sync.aligned.m8n8.x2.trans.shared.b16 {%0,%1}, [%2];"
                        : "=r"(b0), "=r"(b1) : "r"(addr));
                    asm volatile(
                        "mma.sync.aligned.m16n8k16.row.col.f32.f16.f16.f32 "
                        "{%0,%1,%2,%3}, {%4,%5,%6,%7}, {%8,%9}, {%0,%1,%2,%3};"
                        : "+f"(d[ct][qt][0]), "+f"(d[ct][qt][1]),
                          "+f"(d[ct][qt][2]), "+f"(d[ct][qt][3])
                        : "r"(af[kt][0]), "r"(af[kt][1]),
                          "r"(af[kt][2]), "r"(af[kt][3]),
                          "r"(b0), "r"(b1));
                }
            }
        }
    }

    // ---- epilogue: atomicAdd k-partials (out zeroed by proj_kernel) ----
    const int gid = lane >> 2;       // D row within tile
    const int tig = lane & 3;        // D col pair
    #pragma unroll
    for (int ct = 0; ct < 2; ct++)
        #pragma unroll
        for (int qt = 0; qt < 4; qt++) {
            const int c_r = w * 32 + ct * 16 + gid;
            const int q_c = q0 + qt * 8 + tig * 2;
            float* op = out + ((size_t)(b * CV_ + c_r)) * N_ + q_c;
            atomicAdd(op,              d[ct][qt][0]);
            atomicAdd(op + 1,          d[ct][qt][1]);
            atomicAdd(op + 8 * N_,     d[ct][qt][2]);
            atomicAdd(op + 8 * N_ + 1, d[ct][qt][3]);
        }
}

// ============================================================================
extern "C" void kernel_launch(void* const* d_in, const int* in_sizes, int n_in,
                              void* d_out, int out_size)
{
    const float* key   = (const float*)d_in[0];
    const float* query = (const float*)d_in[1];
    const float* value = (const float*)d_in[2];
    const float* Wk    = (const float*)d_in[3];
    const float* bk    = (const float*)d_in[4];
    const float* Wq    = (const float*)d_in[5];
    const float* bq    = (const float*)d_in[6];
    const float* wf    = (const float*)d_in[7];
    const float* bf    = (const float*)d_in[8];
    float* out = (float*)d_out;

    static int attr_set = 0;
    if (!attr_set) {
        cudaFuncSetAttribute(proj_kernel,
                             cudaFuncAttributeMaxDynamicSharedMemorySize,
                             PROJ_SMEM_BYTES);
        attr_set = 1;
    }

    proj_kernel<<<dim3(N_ / 32, B_, 3), 512, PROJ_SMEM_BYTES>>>(
        key, query, value, Wk, bk, Wq, bq, (float4*)out);
    fused_kernel<<<dim3(N_ / 32, KSPLIT, B_), 256>>>(wf, bf, out);
}